// round 1
// baseline (speedup 1.0000x reference)
#include <cuda_runtime.h>

#define NW 18
#define DIM (1u << 18)
#define BATCH 64

// Scratch state buffers (ping-pong needed because the permutation pass writes
// across slab boundaries). 2 x 134 MB static device arrays (allowed scratch).
__device__ float2 g_s0[BATCH * DIM];
__device__ float2 g_s1[BATCH * DIM];
// dd[x] = sum_w head_w[w] * (1 - 2*bit_w(C(x))) : diagonal readout, with the
// final layer's CNOT permutation pre-folded.
__device__ float g_dd[DIM];

// Fused single-qubit gate A = RY(0.1) * RX(0.1):
// A00 = (c^2,  s^2), A01 = (-cs, -cs), A10 = (cs, -cs), A11 = (c^2, -s^2)
// with c = cos(0.05), s = sin(0.05).
#define C2f 0.9975020826390129f
#define S2f 0.0024979173609871f
#define CSf 0.04991670832341407f

__device__ __forceinline__ void bfly(float2& a, float2& b) {
    float nax = C2f * a.x - S2f * a.y - CSf * b.x + CSf * b.y;
    float nay = C2f * a.y + S2f * a.x - CSf * b.y - CSf * b.x;
    float nbx = CSf * a.x + CSf * a.y + C2f * b.x + S2f * b.y;
    float nby = CSf * a.y - CSf * a.x + C2f * b.y - S2f * b.x;
    a.x = nax; a.y = nay; b.x = nbx; b.y = nby;
}

// Apply A on register-index bits 0..NB-1 of a 32-element register array.
template <int NB>
__device__ __forceinline__ void apply_bits(float2 v[32]) {
#pragma unroll
    for (int k = 0; k < NB; k++) {
#pragma unroll
        for (int m = 0; m < 32; m++) {
            if (!(m & (1 << k))) bfly(v[m], v[m | (1 << k)]);
        }
    }
}

// CNOT-ring label permutation for one layer.
// Wire w <-> index bit (17-w). After the chain (0,1)(1,2)...(16,17)(17,0):
//   new bit j (j<=16) = XOR of old bits j..17 ; new bit 17 = XOR of old bits 0..16.
__device__ __forceinline__ unsigned cmap(unsigned x) {
    unsigned sx = x;
    sx ^= sx >> 1; sx ^= sx >> 2; sx ^= sx >> 4; sx ^= sx >> 8; sx ^= sx >> 16;
    return (sx & 0x1FFFFu) | (((sx ^ (x >> 17)) & 1u) << 17);
}

// ---------------------------------------------------------------------------
// LO pass: local bits 0..12 (contiguous 8192-amp slab). Applies A to bits 0..12
// (wires 5..17). Register-blocked: 256 threads x 32 amps. Two padded smem
// transposes rotate which 5 bits live in registers.
// ---------------------------------------------------------------------------
__global__ void __launch_bounds__(256) pass_lo(float2* __restrict__ state,
                                               const float* __restrict__ re,
                                               const float* __restrict__ im,
                                               int first) {
    extern __shared__ float2 sm[];  // 8192 + 256 pad
    const int t = threadIdx.x;
    const int b = blockIdx.x >> 5;
    const int hi = blockIdx.x & 31;
    const size_t base = (size_t)b * DIM + ((size_t)hi << 13);

    float2 v[32];
    if (first) {
#pragma unroll
        for (int r = 0; r < 32; r++) {
            const int j = (r << 8) | t;
            v[r].x = re[base + j];
            v[r].y = im[base + j];
        }
    } else {
#pragma unroll
        for (int r = 0; r < 32; r++) v[r] = state[base + ((r << 8) | t)];
    }

    apply_bits<5>(v);  // reg bits = slab bits 8..12

    // transpose: reg bits -> slab bits 0..4
#pragma unroll
    for (int r = 0; r < 32; r++) { const int j = (r << 8) | t; sm[j + (j >> 5)] = v[r]; }
    __syncthreads();
#pragma unroll
    for (int r = 0; r < 32; r++) { const int j = (t << 5) | r; v[r] = sm[j + (j >> 5)]; }

    apply_bits<5>(v);  // slab bits 0..4

    __syncthreads();
#pragma unroll
    for (int r = 0; r < 32; r++) { const int j = (t << 5) | r; sm[j + (j >> 5)] = v[r]; }
    __syncthreads();
    const int tlo = t & 31, thi = t >> 5;
#pragma unroll
    for (int r = 0; r < 32; r++) {
        const int j = (thi << 10) | (r << 5) | tlo;
        v[r] = sm[j + (j >> 5)];
    }

    apply_bits<3>(v);  // slab bits 5..7 (bits 8,9 = reg bits 3,4 already done)

#pragma unroll
    for (int r = 0; r < 32; r++) {
        const int j = (thi << 10) | (r << 5) | tlo;
        state[base + j] = v[r];
    }
}

// ---------------------------------------------------------------------------
// HI pass: reg bits = index bits 13..17 (wires 0..4); no smem needed.
// Stores through the CNOT-ring permutation C (maps low 5 bits to low 5 bits,
// so stores remain 256B-coalesced per warp). src != dst (ping-pong).
// ---------------------------------------------------------------------------
__global__ void __launch_bounds__(256) pass_hi(const float2* __restrict__ src,
                                               float2* __restrict__ dst) {
    const int t = threadIdx.x;
    const int b = blockIdx.x >> 5;
    const int mid = blockIdx.x & 31;
    const size_t bb = (size_t)b * DIM;

    float2 v[32];
#pragma unroll
    for (int r = 0; r < 32; r++) {
        const unsigned x = ((unsigned)r << 13) | ((unsigned)mid << 8) | (unsigned)t;
        v[r] = src[bb + x];
    }

    apply_bits<5>(v);  // bits 13..17

#pragma unroll
    for (int r = 0; r < 32; r++) {
        const unsigned x = ((unsigned)r << 13) | ((unsigned)mid << 8) | (unsigned)t;
        dst[bb + cmap(x)] = v[r];
    }
}

// ---------------------------------------------------------------------------
// Final pass: HI gates of layer 3, then weighted |.|^2 reduction with dd[x]
// (layer-3 permutation pre-folded into dd). No state store.
// ---------------------------------------------------------------------------
__global__ void __launch_bounds__(256) pass_reduce(const float2* __restrict__ src,
                                                   float* __restrict__ out) {
    const int t = threadIdx.x;
    const int b = blockIdx.x >> 5;
    const int mid = blockIdx.x & 31;
    const size_t bb = (size_t)b * DIM;

    float2 v[32];
#pragma unroll
    for (int r = 0; r < 32; r++) {
        const unsigned x = ((unsigned)r << 13) | ((unsigned)mid << 8) | (unsigned)t;
        v[r] = src[bb + x];
    }

    apply_bits<5>(v);

    float acc = 0.0f;
#pragma unroll
    for (int r = 0; r < 32; r++) {
        const unsigned x = ((unsigned)r << 13) | ((unsigned)mid << 8) | (unsigned)t;
        acc += g_dd[x] * (v[r].x * v[r].x + v[r].y * v[r].y);
    }

#pragma unroll
    for (int o = 16; o; o >>= 1) acc += __shfl_xor_sync(0xFFFFFFFFu, acc, o);
    __shared__ float ws[8];
    if ((t & 31) == 0) ws[t >> 5] = acc;
    __syncthreads();
    if (t < 8) {
        float s = ws[t];
#pragma unroll
        for (int o = 4; o; o >>= 1) s += __shfl_xor_sync(0xFFu, s, o);
        if (t == 0) atomicAdd(out + b, s);
    }
}

// ---------------------------------------------------------------------------
// Init: build dd[] table and seed out[b] = head_b (out is poisoned each run).
// ---------------------------------------------------------------------------
__global__ void __launch_bounds__(256) init_kernel(const float* __restrict__ hw,
                                                   const float* __restrict__ hb,
                                                   float* __restrict__ out) {
    const unsigned x = blockIdx.x * 256u + threadIdx.x;
    if (x < DIM) {
        const unsigned y = cmap(x);
        float d = 0.0f;
#pragma unroll
        for (int w = 0; w < NW; w++) {
            d += hw[w] * (((y >> (17 - w)) & 1u) ? -1.0f : 1.0f);
        }
        g_dd[x] = d;
    }
    if (x < BATCH) out[x] = hb[0];
}

extern "C" void kernel_launch(void* const* d_in, const int* in_sizes, int n_in,
                              void* d_out, int out_size) {
    (void)in_sizes; (void)n_in; (void)out_size;
    const float* re = (const float*)d_in[0];
    const float* im = (const float*)d_in[1];
    const float* hw = (const float*)d_in[2];
    const float* hb = (const float*)d_in[3];
    float* out = (float*)d_out;

    float2 *s0, *s1;
    cudaGetSymbolAddress((void**)&s0, g_s0);
    cudaGetSymbolAddress((void**)&s1, g_s1);

    const int smemLO = (8192 + 256) * (int)sizeof(float2);  // 67.5 KB
    cudaFuncSetAttribute(pass_lo, cudaFuncAttributeMaxDynamicSharedMemorySize, smemLO);

    const int grid = BATCH * 32;  // 2048 CTAs

    init_kernel<<<DIM / 256, 256>>>(hw, hb, out);

    // Layer 1
    pass_lo<<<grid, 256, smemLO>>>(s0, re, im, 1);   // input -> s0, A on bits 0..12
    pass_hi<<<grid, 256>>>(s0, s1);                  // A on bits 13..17, then CNOT perm
    // Layer 2
    pass_lo<<<grid, 256, smemLO>>>(s1, re, im, 0);
    pass_hi<<<grid, 256>>>(s1, s0);
    // Layer 3
    pass_lo<<<grid, 256, smemLO>>>(s0, re, im, 0);
    pass_reduce<<<grid, 256>>>(s0, out);             // A bits 13..17 + perm-folded readout
}

// round 2
// speedup vs baseline: 1.0104x; 1.0104x over previous
#include <cuda_runtime.h>

#define NW 18
#define DIM (1u << 18)
#define BATCH 64

// Scratch state buffers (ping-pong needed because the permutation pass writes
// across slab boundaries). 2 x 134 MB static device arrays (allowed scratch).
__device__ float2 g_s0[BATCH * DIM];
__device__ float2 g_s1[BATCH * DIM];
// dd[x] = sum_w head_w[w] * (1 - 2*bit_w(C(x))) : diagonal readout, with the
// final layer's CNOT permutation pre-folded.
__device__ float g_dd[DIM];

// Fused single-qubit gate A = RY(0.1) * RX(0.1):
// A00 = (c^2,  s^2), A01 = (-cs, -cs), A10 = (cs, -cs), A11 = (c^2, -s^2)
// with c = cos(0.05), s = sin(0.05).
#define C2f 0.9975020826390129f
#define S2f 0.0024979173609871f
#define CSf 0.04991670832341407f

__device__ __forceinline__ void bfly(float2& a, float2& b) {
    float nax = C2f * a.x - S2f * a.y - CSf * b.x + CSf * b.y;
    float nay = C2f * a.y + S2f * a.x - CSf * b.y - CSf * b.x;
    float nbx = CSf * a.x + CSf * a.y + C2f * b.x + S2f * b.y;
    float nby = CSf * a.y - CSf * a.x + C2f * b.y - S2f * b.x;
    a.x = nax; a.y = nay; b.x = nbx; b.y = nby;
}

// Apply A on register-index bits 0..NB-1 of a 32-element register array.
template <int NB>
__device__ __forceinline__ void apply_bits(float2 v[32]) {
#pragma unroll
    for (int k = 0; k < NB; k++) {
#pragma unroll
        for (int m = 0; m < 32; m++) {
            if (!(m & (1 << k))) bfly(v[m], v[m | (1 << k)]);
        }
    }
}

// CNOT-ring label permutation for one layer.
// Wire w <-> index bit (17-w). After the chain (0,1)(1,2)...(16,17)(17,0):
//   new bit j (j<=16) = XOR of old bits j..17 ; new bit 17 = XOR of old bits 0..16.
__device__ __forceinline__ unsigned cmap(unsigned x) {
    unsigned sx = x;
    sx ^= sx >> 1; sx ^= sx >> 2; sx ^= sx >> 4; sx ^= sx >> 8; sx ^= sx >> 16;
    return (sx & 0x1FFFFu) | (((sx ^ (x >> 17)) & 1u) << 17);
}

// ---------------------------------------------------------------------------
// LO pass: local bits 0..12 (contiguous 8192-amp slab). Applies A to bits 0..12
// (wires 5..17). Register-blocked: 256 threads x 32 amps. Two padded smem
// transposes rotate which 5 bits live in registers.
// ---------------------------------------------------------------------------
__global__ void __launch_bounds__(256) pass_lo(float2* __restrict__ state,
                                               const float* __restrict__ re,
                                               const float* __restrict__ im,
                                               int first) {
    extern __shared__ float2 sm[];  // 8192 + 256 pad
    const int t = threadIdx.x;
    const int b = blockIdx.x >> 5;
    const int hi = blockIdx.x & 31;
    const size_t base = (size_t)b * DIM + ((size_t)hi << 13);

    float2 v[32];
    if (first) {
#pragma unroll
        for (int r = 0; r < 32; r++) {
            const int j = (r << 8) | t;
            v[r].x = re[base + j];
            v[r].y = im[base + j];
        }
    } else {
#pragma unroll
        for (int r = 0; r < 32; r++) v[r] = state[base + ((r << 8) | t)];
    }

    apply_bits<5>(v);  // reg bits = slab bits 8..12

    // transpose: reg bits -> slab bits 0..4
#pragma unroll
    for (int r = 0; r < 32; r++) { const int j = (r << 8) | t; sm[j + (j >> 5)] = v[r]; }
    __syncthreads();
#pragma unroll
    for (int r = 0; r < 32; r++) { const int j = (t << 5) | r; v[r] = sm[j + (j >> 5)]; }

    apply_bits<5>(v);  // slab bits 0..4

    __syncthreads();
#pragma unroll
    for (int r = 0; r < 32; r++) { const int j = (t << 5) | r; sm[j + (j >> 5)] = v[r]; }
    __syncthreads();
    const int tlo = t & 31, thi = t >> 5;
#pragma unroll
    for (int r = 0; r < 32; r++) {
        const int j = (thi << 10) | (r << 5) | tlo;
        v[r] = sm[j + (j >> 5)];
    }

    apply_bits<3>(v);  // slab bits 5..7 (bits 8,9 = reg bits 3,4 already done)

#pragma unroll
    for (int r = 0; r < 32; r++) {
        const int j = (thi << 10) | (r << 5) | tlo;
        state[base + j] = v[r];
    }
}

// ---------------------------------------------------------------------------
// HI pass: reg bits = index bits 13..17 (wires 0..4); no smem needed.
// Stores through the CNOT-ring permutation C (maps low 5 bits to low 5 bits,
// so stores remain 256B-coalesced per warp). src != dst (ping-pong).
// ---------------------------------------------------------------------------
__global__ void __launch_bounds__(256) pass_hi(const float2* __restrict__ src,
                                               float2* __restrict__ dst) {
    const int t = threadIdx.x;
    const int b = blockIdx.x >> 5;
    const int mid = blockIdx.x & 31;
    const size_t bb = (size_t)b * DIM;

    float2 v[32];
#pragma unroll
    for (int r = 0; r < 32; r++) {
        const unsigned x = ((unsigned)r << 13) | ((unsigned)mid << 8) | (unsigned)t;
        v[r] = src[bb + x];
    }

    apply_bits<5>(v);  // bits 13..17

#pragma unroll
    for (int r = 0; r < 32; r++) {
        const unsigned x = ((unsigned)r << 13) | ((unsigned)mid << 8) | (unsigned)t;
        dst[bb + cmap(x)] = v[r];
    }
}

// ---------------------------------------------------------------------------
// Final pass: HI gates of layer 3, then weighted |.|^2 reduction with dd[x]
// (layer-3 permutation pre-folded into dd). No state store.
// ---------------------------------------------------------------------------
__global__ void __launch_bounds__(256) pass_reduce(const float2* __restrict__ src,
                                                   float* __restrict__ out) {
    const int t = threadIdx.x;
    const int b = blockIdx.x >> 5;
    const int mid = blockIdx.x & 31;
    const size_t bb = (size_t)b * DIM;

    float2 v[32];
#pragma unroll
    for (int r = 0; r < 32; r++) {
        const unsigned x = ((unsigned)r << 13) | ((unsigned)mid << 8) | (unsigned)t;
        v[r] = src[bb + x];
    }

    apply_bits<5>(v);

    float acc = 0.0f;
#pragma unroll
    for (int r = 0; r < 32; r++) {
        const unsigned x = ((unsigned)r << 13) | ((unsigned)mid << 8) | (unsigned)t;
        acc += g_dd[x] * (v[r].x * v[r].x + v[r].y * v[r].y);
    }

#pragma unroll
    for (int o = 16; o; o >>= 1) acc += __shfl_xor_sync(0xFFFFFFFFu, acc, o);
    __shared__ float ws[8];
    if ((t & 31) == 0) ws[t >> 5] = acc;
    __syncthreads();
    if (t < 8) {
        float s = ws[t];
#pragma unroll
        for (int o = 4; o; o >>= 1) s += __shfl_xor_sync(0xFFu, s, o);
        if (t == 0) atomicAdd(out + b, s);
    }
}

// ---------------------------------------------------------------------------
// Init: build dd[] table and seed out[b] = head_b (out is poisoned each run).
// ---------------------------------------------------------------------------
__global__ void __launch_bounds__(256) init_kernel(const float* __restrict__ hw,
                                                   const float* __restrict__ hb,
                                                   float* __restrict__ out) {
    const unsigned x = blockIdx.x * 256u + threadIdx.x;
    if (x < DIM) {
        const unsigned y = cmap(x);
        float d = 0.0f;
#pragma unroll
        for (int w = 0; w < NW; w++) {
            d += hw[w] * (((y >> (17 - w)) & 1u) ? -1.0f : 1.0f);
        }
        g_dd[x] = d;
    }
    if (x < BATCH) out[x] = hb[0];
}

extern "C" void kernel_launch(void* const* d_in, const int* in_sizes, int n_in,
                              void* d_out, int out_size) {
    (void)in_sizes; (void)n_in; (void)out_size;
    const float* re = (const float*)d_in[0];
    const float* im = (const float*)d_in[1];
    const float* hw = (const float*)d_in[2];
    const float* hb = (const float*)d_in[3];
    float* out = (float*)d_out;

    float2 *s0, *s1;
    cudaGetSymbolAddress((void**)&s0, g_s0);
    cudaGetSymbolAddress((void**)&s1, g_s1);

    const int smemLO = (8192 + 256) * (int)sizeof(float2);  // 67.5 KB
    cudaFuncSetAttribute(pass_lo, cudaFuncAttributeMaxDynamicSharedMemorySize, smemLO);

    const int grid = BATCH * 32;  // 2048 CTAs

    init_kernel<<<DIM / 256, 256>>>(hw, hb, out);

    // Layer 1
    pass_lo<<<grid, 256, smemLO>>>(s0, re, im, 1);   // input -> s0, A on bits 0..12
    pass_hi<<<grid, 256>>>(s0, s1);                  // A on bits 13..17, then CNOT perm
    // Layer 2
    pass_lo<<<grid, 256, smemLO>>>(s1, re, im, 0);
    pass_hi<<<grid, 256>>>(s1, s0);
    // Layer 3
    pass_lo<<<grid, 256, smemLO>>>(s0, re, im, 0);
    pass_reduce<<<grid, 256>>>(s0, out);             // A bits 13..17 + perm-folded readout
}

// round 3
// speedup vs baseline: 1.4831x; 1.4678x over previous
#include <cuda_runtime.h>
#include <cuda_fp16.h>
#include <math.h>

#define DIM (1u << 18)
#define CELLS (1u << 17)
#define BATCH 64

typedef unsigned long long pk;  // packed f32x2 (lane0 = low word = even amp)

// fp16 SoA planes, ping-pong. 4 x 32 MB static scratch.
__device__ __half2 g_x0[BATCH * CELLS];
__device__ __half2 g_y0[BATCH * CELLS];
__device__ __half2 g_x1[BATCH * CELLS];
__device__ __half2 g_y1[BATCH * CELLS];
// Readout diagonal dd[x] (CNOT perm + (c^2)^108 + 1/256 folded in).
__device__ __align__(8) float g_dd[DIM];

#define TAU 0.05004170837554f  // tan(0.05); gate A/c^2 = I + tau*(..) + tau^2*(..)

__device__ __forceinline__ pk pack2(float lo, float hi) {
    pk r; asm("mov.b64 %0,{%1,%2};" : "=l"(r) : "f"(lo), "f"(hi)); return r;
}
__device__ __forceinline__ void unpack2(pk p, float& lo, float& hi) {
    asm("mov.b64 {%0,%1},%2;" : "=f"(lo), "=f"(hi) : "l"(p));
}
__device__ __forceinline__ pk fma2(pk a, pk b, pk c) {
    pk d; asm("fma.rn.f32x2 %0,%1,%2,%3;" : "=l"(d) : "l"(a), "l"(b), "l"(c)); return d;
}
__device__ __forceinline__ pk mul2(pk a, pk b) {
    pk d; asm("mul.rn.f32x2 %0,%1,%2;" : "=l"(d) : "l"(a), "l"(b)); return d;
}
__device__ __forceinline__ pk swap2(pk p) { float lo, hi; unpack2(p, lo, hi); return pack2(hi, lo); }

struct KC { pk Tp, Tn, T2p, T2n; };
__device__ __forceinline__ KC mkKC() {
    const float t = TAU, t2 = TAU * TAU;
    KC k; k.Tp = pack2(t, t); k.Tn = pack2(-t, -t);
    k.T2p = pack2(t2, t2); k.T2n = pack2(-t2, -t2); return k;
}

// Two independent scaled butterflies (one per SIMD lane), 12 fma2.
// a' = a - t2*ia.. per: nax = ax - t2*ay - t*bx + t*by, etc. (x true = c^2 * these)
__device__ __forceinline__ void bfly2t(pk& Xa, pk& Ya, pk& Xb, pk& Yb, const KC& k) {
    pk nXa = fma2(Yb, k.Tp, fma2(Xb, k.Tn, fma2(Ya, k.T2n, Xa)));
    pk nYa = fma2(Yb, k.Tn, fma2(Xb, k.Tn, fma2(Xa, k.T2p, Ya)));
    pk nXb = fma2(Xa, k.Tp, fma2(Ya, k.Tp, fma2(Yb, k.T2p, Xb)));
    pk nYb = fma2(Xa, k.Tn, fma2(Ya, k.Tp, fma2(Xb, k.T2n, Yb)));
    Xa = nXa; Ya = nYa; Xb = nXb; Yb = nYb;
}

// Gate on 4 register-index bits of a 16-pack array.
__device__ __forceinline__ void clean4(pk X[16], pk Y[16], const KC& k) {
#pragma unroll
    for (int bit = 0; bit < 4; bit++)
#pragma unroll
        for (int m = 0; m < 16; m++)
            if (!(m & (1 << bit))) {
                const int n = m | (1 << bit);
                bfly2t(X[m], Y[m], X[n], Y[n], k);
            }
}

// Gate on global bit 0 (the SIMD lane inside the pack).
__device__ __forceinline__ void bflyL(pk& X, pk& Y, const KC& k) {
    const float t = TAU, t2 = TAU * TAU;
    const pk Tm = pack2(-t, t), T2m = pack2(-t2, t2), T2m2 = pack2(t2, -t2);
    pk sX = swap2(X), sY = swap2(Y);
    pk nX = fma2(sY, k.Tp, fma2(sX, Tm, fma2(Y, T2m, X)));
    pk nY = fma2(sY, Tm, fma2(sX, k.Tn, fma2(X, T2m2, Y)));
    X = nX; Y = nY;
}

// CNOT-ring label permutation (wire w <-> bit 17-w). Linear over XOR.
__device__ __forceinline__ unsigned cmap(unsigned x) {
    unsigned sx = x;
    sx ^= sx >> 1; sx ^= sx >> 2; sx ^= sx >> 4; sx ^= sx >> 8; sx ^= sx >> 16;
    return (sx & 0x1FFFFu) | (((sx ^ (x >> 17)) & 1u) << 18 >> 1); // bit17 = sx0 ^ x17
}

#define PADC(c) ((c) + ((c) >> 4))

// ---------------------------------------------------------------------------
// LO pass: gates on x bits 0..12. Slab = 4096 cells (8192 amps). 256 thr x 16 packs.
// Phases: bit0 (SIMD) | cell bits 4..7 | 0..3 | 8..11 with 3 padded smem transposes.
// In-place (slab-local). first=1 reads fp32 input (x16).
// ---------------------------------------------------------------------------
__global__ void __launch_bounds__(256, 2) pass_lo(__half2* __restrict__ px,
                                                  __half2* __restrict__ py,
                                                  const float* __restrict__ re,
                                                  const float* __restrict__ im,
                                                  int first) {
    extern __shared__ pk sm[];
    pk* sx = sm;          // 4352
    pk* sy = sm + 4352;   // 4352
    const int t = threadIdx.x;
    const unsigned b = blockIdx.x >> 5, hi = blockIdx.x & 31;
    const size_t cb = ((size_t)b << 17) | ((size_t)hi << 12);
    const KC k = mkKC();

    pk X[16], Y[16];
    if (first) {
        const pk s16 = pack2(16.0f, 16.0f);
#pragma unroll
        for (int r = 0; r < 16; r++) {
            const size_t a = (cb + (unsigned)((r << 8) | t)) * 2;
            X[r] = mul2(*(const pk*)(re + a), s16);
            Y[r] = mul2(*(const pk*)(im + a), s16);
        }
    } else {
#pragma unroll
        for (int r = 0; r < 16; r++) {
            const size_t c = cb + (unsigned)((r << 8) | t);
            float2 fx = __half22float2(px[c]);
            float2 fy = __half22float2(py[c]);
            X[r] = pack2(fx.x, fx.y);
            Y[r] = pack2(fy.x, fy.y);
        }
    }

#pragma unroll
    for (int m = 0; m < 16; m++) bflyL(X[m], Y[m], k);   // x bit 0

    // layout0 (r<<8|t) -> layout1: reg = cell bits 4..7 (x bits 5..8)
#pragma unroll
    for (int r = 0; r < 16; r++) { const unsigned c = (r << 8) | t; sx[PADC(c)] = X[r]; sy[PADC(c)] = Y[r]; }
    __syncthreads();
#pragma unroll
    for (int r = 0; r < 16; r++) {
        const unsigned c = ((t >> 4) << 8) | (r << 4) | (t & 15);
        X[r] = sx[PADC(c)]; Y[r] = sy[PADC(c)];
    }
    clean4(X, Y, k);
    __syncthreads();

    // layout1 -> layout2: reg = cell bits 0..3 (x bits 1..4)
#pragma unroll
    for (int r = 0; r < 16; r++) {
        const unsigned c = ((t >> 4) << 8) | (r << 4) | (t & 15);
        sx[PADC(c)] = X[r]; sy[PADC(c)] = Y[r];
    }
    __syncthreads();
#pragma unroll
    for (int r = 0; r < 16; r++) {
        const unsigned c = (t << 4) | r;
        X[r] = sx[PADC(c)]; Y[r] = sy[PADC(c)];
    }
    clean4(X, Y, k);
    __syncthreads();

    // layout2 -> layout0: reg = cell bits 8..11 (x bits 9..12); store coalesced
#pragma unroll
    for (int r = 0; r < 16; r++) { const unsigned c = (t << 4) | r; sx[PADC(c)] = X[r]; sy[PADC(c)] = Y[r]; }
    __syncthreads();
#pragma unroll
    for (int r = 0; r < 16; r++) { const unsigned c = (r << 8) | t; X[r] = sx[PADC(c)]; Y[r] = sy[PADC(c)]; }
    clean4(X, Y, k);

#pragma unroll
    for (int r = 0; r < 16; r++) {
        const size_t c = cb + (unsigned)((r << 8) | t);
        float a0, a1;
        unpack2(X[r], a0, a1); px[c] = __floats2half2_rn(a0, a1);
        unpack2(Y[r], a0, a1); py[c] = __floats2half2_rn(a0, a1);
    }
}

// ---------------------------------------------------------------------------
// HI gates (x bits 13..17): cell bits 12..15 = reg r, cell bit 16 = lane bit 4.
// ---------------------------------------------------------------------------
__device__ __forceinline__ void hi_load_gates(const __half2* __restrict__ sx,
                                              const __half2* __restrict__ sy,
                                              size_t bb, unsigned clo, int L4,
                                              const KC& k, pk X[16], pk Y[16]) {
#pragma unroll
    for (int r = 0; r < 16; r++) {
        const size_t c = bb + (clo | ((unsigned)r << 12));
        float2 fx = __half22float2(sx[c]);
        float2 fy = __half22float2(sy[c]);
        X[r] = pack2(fx.x, fx.y);
        Y[r] = pack2(fy.x, fy.y);
    }
    clean4(X, Y, k);   // x bits 13..16

    // x bit 17 via shfl_xor(16); a-side (L4=0): e=-1, b-side: e=+1
    const float e = L4 ? TAU : -TAU;
    const pk eT = pack2(e, e), eT2 = pack2(e * TAU, e * TAU), eT2n = pack2(-e * TAU, -e * TAU);
#pragma unroll
    for (int r = 0; r < 16; r++) {
        pk pX = __shfl_xor_sync(0xffffffffu, X[r], 16);
        pk pY = __shfl_xor_sync(0xffffffffu, Y[r], 16);
        pk nX = fma2(pY, k.Tp, fma2(pX, eT, fma2(Y[r], eT2, X[r])));
        pk nY = fma2(pY, eT, fma2(pX, k.Tn, fma2(X[r], eT2n, Y[r])));
        X[r] = nX; Y[r] = nY;
    }
}

// ---------------------------------------------------------------------------
// HI pass + CNOT permutation folded into the store.
// dst cell pair (y, y^1): sources x_even and x_even^0x30001. Partner pack lives
// at (lane^16, reg^8); reassembled with prmt, parity-selected.
// ---------------------------------------------------------------------------
__global__ void __launch_bounds__(256) pass_hi(const __half2* __restrict__ sx,
                                               const __half2* __restrict__ sy,
                                               __half2* __restrict__ dx,
                                               __half2* __restrict__ dy) {
    const int t = threadIdx.x, L = t & 31, W = t >> 5, L4 = (L >> 4) & 1;
    const unsigned b = blockIdx.x >> 5, mid = blockIdx.x & 31;
    const size_t bb = (size_t)b << 17;
    const unsigned clo = (mid << 7) | (W << 4) | (unsigned)(L & 15) | ((unsigned)L4 << 16);
    const KC k = mkKC();

    pk X[16], Y[16];
    hi_load_gates(sx, sy, bb, clo, L4, k, X, Y);

    unsigned hx[16], hy[16];
#pragma unroll
    for (int r = 0; r < 16; r++) {
        float a0, a1;
        unpack2(X[r], a0, a1); __half2 h = __floats2half2_rn(a0, a1); hx[r] = *(unsigned*)&h;
        unpack2(Y[r], a0, a1); h = __floats2half2_rn(a0, a1); hy[r] = *(unsigned*)&h;
    }

    const unsigned cB = cmap(clo << 1);       // cmap of this thread's x base (bit0=0)
    const int pbase = __popc(clo) & 1;
#pragma unroll
    for (int r = 0; r < 16; r++) {
        const unsigned phx = __shfl_xor_sync(0xffffffffu, hx[r ^ 8], 16);
        const unsigned phy = __shfl_xor_sync(0xffffffffu, hy[r ^ 8], 16);
        const int pr = pbase ^ (__popc((unsigned)r) & 1);   // parity(x)
        const unsigned ctrl = pr ? 0x5432u : 0x7610u;       // (own.hi,part.lo) : (own.lo,part.hi)
        const unsigned ox = __byte_perm(hx[r], phx, ctrl);
        const unsigned oy = __byte_perm(hy[r], phy, ctrl);
        const unsigned y = cB ^ cmap((unsigned)r << 13) ^ (pr ? 0x20001u : 0u);
        const size_t dc = bb + (y >> 1);
        dx[dc] = *(const __half2*)&ox;
        dy[dc] = *(const __half2*)&oy;
    }
}

// ---------------------------------------------------------------------------
// Final: HI gates of layer 3 + weighted |.|^2 readout (perm + scales in dd).
// ---------------------------------------------------------------------------
__global__ void __launch_bounds__(256) pass_reduce(const __half2* __restrict__ sx,
                                                   const __half2* __restrict__ sy,
                                                   float* __restrict__ out) {
    const int t = threadIdx.x, L = t & 31, W = t >> 5, L4 = (L >> 4) & 1;
    const unsigned b = blockIdx.x >> 5, mid = blockIdx.x & 31;
    const size_t bb = (size_t)b << 17;
    const unsigned clo = (mid << 7) | (W << 4) | (unsigned)(L & 15) | ((unsigned)L4 << 16);
    const KC k = mkKC();

    pk X[16], Y[16];
    hi_load_gates(sx, sy, bb, clo, L4, k, X, Y);

    pk acc = pack2(0.0f, 0.0f);
#pragma unroll
    for (int r = 0; r < 16; r++) {
        const size_t c = (size_t)(clo | ((unsigned)r << 12));
        const pk dpk = *(const pk*)(g_dd + (c << 1));
        pk p2 = fma2(Y[r], Y[r], mul2(X[r], X[r]));
        acc = fma2(p2, dpk, acc);
    }
    float a0, a1; unpack2(acc, a0, a1);
    float a = a0 + a1;
#pragma unroll
    for (int o = 16; o; o >>= 1) a += __shfl_xor_sync(0xffffffffu, a, o);
    __shared__ float ws[8];
    if (L == 0) ws[W] = a;
    __syncthreads();
    if (t < 8) {
        float s = ws[t];
#pragma unroll
        for (int o = 4; o; o >>= 1) s += __shfl_xor_sync(0xffu, s, o);
        if (t == 0) atomicAdd(out + b, s);
    }
}

// ---------------------------------------------------------------------------
// Init dd[] and out[b] = head_b (out is poisoned before each timed run).
// ---------------------------------------------------------------------------
__global__ void __launch_bounds__(256) init_kernel(const float* __restrict__ hw,
                                                   const float* __restrict__ hb,
                                                   float* __restrict__ out, float scale) {
    const unsigned x = blockIdx.x * 256u + threadIdx.x;
    if (x < DIM) {
        const unsigned y = cmap(x);
        float d = 0.0f;
#pragma unroll
        for (int w = 0; w < 18; w++)
            d += hw[w] * (((y >> (17 - w)) & 1u) ? -1.0f : 1.0f);
        g_dd[x] = d * scale;
    }
    if (x < BATCH) out[x] = hb[0];
}

extern "C" void kernel_launch(void* const* d_in, const int* in_sizes, int n_in,
                              void* d_out, int out_size) {
    (void)in_sizes; (void)n_in; (void)out_size;
    const float* re = (const float*)d_in[0];
    const float* im = (const float*)d_in[1];
    const float* hw = (const float*)d_in[2];
    const float* hb = (const float*)d_in[3];
    float* out = (float*)d_out;

    __half2 *x0, *y0, *x1, *y1;
    cudaGetSymbolAddress((void**)&x0, g_x0);
    cudaGetSymbolAddress((void**)&y0, g_y0);
    cudaGetSymbolAddress((void**)&x1, g_x1);
    cudaGetSymbolAddress((void**)&y1, g_y1);

    const int smemLO = 2 * 4352 * (int)sizeof(pk);  // 69632 B
    cudaFuncSetAttribute(pass_lo, cudaFuncAttributeMaxDynamicSharedMemorySize, smemLO);

    // deferred gate scale: (c^2)^108 for probs; /256 for the x16 input scaling
    const float scale = (float)(pow(0.9975020826390129, 108.0) / 256.0);

    const int grid = BATCH * 32;  // 2048

    init_kernel<<<DIM / 256, 256>>>(hw, hb, out, scale);

    // Layer 1
    pass_lo<<<grid, 256, smemLO>>>(x0, y0, re, im, 1);
    pass_hi<<<grid, 256>>>(x0, y0, x1, y1);
    // Layer 2
    pass_lo<<<grid, 256, smemLO>>>(x1, y1, re, im, 0);
    pass_hi<<<grid, 256>>>(x1, y1, x0, y0);
    // Layer 3
    pass_lo<<<grid, 256, smemLO>>>(x0, y0, re, im, 0);
    pass_reduce<<<grid, 256>>>(x0, y0, out);
}